// round 13
// baseline (speedup 1.0000x reference)
#include <cuda_runtime.h>
#include <cuda_fp16.h>
#include <math.h>
#include <stdint.h>

// Problem constants
#define BATCH 4
#define NTOK  2048
#define FEATS 1024
#define NHEAD 16
#define HDIM  64
#define MROWS (BATCH * NTOK)   // 8192
#define WSZ   (1024 * 1024)

// ---------------- scratch (device globals) ----------------
__device__ float  g_S[64 * HDIM * HDIM];
__device__ float  g_Sp[1024 * HDIM * HDIM];   // 16 MB: 16 partials per (b,h)
__device__ __half g_xh[MROWS * FEATS];
__device__ __half g_qh[MROWS * FEATS];
__device__ __half g_kh[MROWS * FEATS];
__device__ __half g_vh[MROWS * FEATS];
__device__ __half g_ah[MROWS * FEATS];
__device__ __half g_wth[4 * WSZ];   // Wq/Wk/Wv/Wo transposed [N,K] fp16

// ==================== PTX helpers ====================
#define CP_ASYNC16(dst, src) \
    asm volatile("cp.async.cg.shared.global [%0], [%1], 16;\n" :: "r"(dst), "l"(src))
#define CP_COMMIT() asm volatile("cp.async.commit_group;\n")
#define CP_WAIT2()  asm volatile("cp.async.wait_group 2;\n" ::: "memory")
#define CP_WAIT1()  asm volatile("cp.async.wait_group 1;\n" ::: "memory")
#define CP_WAIT0()  asm volatile("cp.async.wait_group 0;\n" ::: "memory")

#define LDMATRIX_X4(r0,r1,r2,r3,addr) \
    asm volatile("ldmatrix.sync.aligned.m8n8.x4.shared.b16 {%0,%1,%2,%3}, [%4];" \
        : "=r"(r0),"=r"(r1),"=r"(r2),"=r"(r3) : "r"(addr))
#define LDMATRIX_X4_T(r0,r1,r2,r3,addr) \
    asm volatile("ldmatrix.sync.aligned.m8n8.x4.trans.shared.b16 {%0,%1,%2,%3}, [%4];" \
        : "=r"(r0),"=r"(r1),"=r"(r2),"=r"(r3) : "r"(addr))
#define MMA16816(c0,c1,c2,c3,a0,a1,a2,a3,b0,b1) \
    asm volatile("mma.sync.aligned.m16n8k16.row.col.f32.f16.f16.f32 " \
        "{%0,%1,%2,%3},{%4,%5,%6,%7},{%8,%9},{%0,%1,%2,%3};" \
        : "+f"(c0),"+f"(c1),"+f"(c2),"+f"(c3) \
        : "r"(a0),"r"(a1),"r"(a2),"r"(a3),"r"(b0),"r"(b1))

// ==================== merged prep: x->fp16 + W transpose->fp16 ====================
// blocks [0, 8192): tofp16 over x (float4 per thread)
// blocks [8192, 12288): wsplit, flat-indexed (z = wb>>10, k0/n0 from low bits)
__global__ __launch_bounds__(256) void prep_kernel(
    const float* __restrict__ x,
    const float* __restrict__ W0, const float* __restrict__ W1,
    const float* __restrict__ W2, const float* __restrict__ W3,
    __half* __restrict__ xh, __half* __restrict__ wth)
{
    __shared__ float t[32][33];
    int bx = blockIdx.x;
    int tid = threadIdx.x;
    if (bx < 8192) {
        int i = bx * 256 + tid;     // exactly MROWS*FEATS/4 elements
        float4 v = ((const float4*)x)[i];
        __half2* hp = (__half2*)xh;
        hp[i*2]   = __half2(__float2half_rn(v.x), __float2half_rn(v.y));
        hp[i*2+1] = __half2(__float2half_rn(v.z), __float2half_rn(v.w));
    } else {
        int wb = bx - 8192;
        int z = wb >> 10;
        int rest = wb & 1023;
        int n0 = (rest & 31) * 32;
        int k0 = (rest >> 5) * 32;
        const float* W = (z == 0) ? W0 : (z == 1) ? W1 : (z == 2) ? W2 : W3;
        __half* ho = wth + (size_t)z * WSZ;
        int tx = tid & 31, ty = tid >> 5;  // 32 x 8
        #pragma unroll
        for (int i = 0; i < 32; i += 8)
            t[ty + i][tx] = W[(size_t)(k0 + ty + i) * 1024 + n0 + tx];
        __syncthreads();
        #pragma unroll
        for (int i = 0; i < 32; i += 8)
            ho[(size_t)(n0 + ty + i) * 1024 + k0 + tx] = __float2half_rn(t[tx][ty + i]);
    }
}

// ==================== mma.sync fp16 GEMM ====================
// C = A @ B^T + bias  (B stored [N,K] fp16)
// Tile 128x128, 8 warps (2M x 4N), warp tile 64x32, chunk K=32, 4-stage.
#define TBM 128
#define TBN 128
#define TKC 32
#define NCH 32
#define APITCH 40
#define TILE_B (128 * APITCH * 2)   // 10240 bytes per tile
#define STG (2 * TILE_B)            // 20480 (A, B)
#define NST 4
#define GSMEM (NST * STG)           // 81920

__global__ __launch_bounds__(256, 2) void gemm1_kernel(
    const __half* __restrict__ Ah, const __half* __restrict__ Wth,
    const float* __restrict__ b0, const float* __restrict__ b1,
    const float* __restrict__ b2,
    float* __restrict__ C0,
    __half* __restrict__ H0, __half* __restrict__ H1, __half* __restrict__ H2,
    int normFlag, int fp16out)
{
    extern __shared__ __align__(128) char dsm[];
    const uint32_t sb = (uint32_t)__cvta_generic_to_shared(dsm);

    const int tid = threadIdx.x;
    const int lane = tid & 31;
    const int wid = tid >> 5;
    const int wm = wid & 1;        // 0..1 -> 64-row half
    const int wn = wid >> 1;       // 0..3 -> 32-col quarter
    const int z = blockIdx.z;
    const int row0 = blockIdx.y * TBM;
    const int col0 = blockIdx.x * TBN;

    const __half* Bh = Wth + (size_t)z * WSZ;
    const float* bias = (z == 0) ? b0 : (z == 1) ? b1 : b2;

    // cp.async addressing
    const int ld_r  = tid >> 2;
    const int ld_c  = (tid & 3) * 8;
    const uint32_t ld_dst = (uint32_t)((ld_r * APITCH + ld_c) * 2);

    auto issue = [&](int c) {
        const int kk = c * TKC;
        const uint32_t st = sb + (c & (NST - 1)) * STG;
        #pragma unroll
        for (int i = 0; i < 2; i++) {
            uint32_t d = st + ld_dst + i * 64 * APITCH * 2;
            CP_ASYNC16(d, Ah + (size_t)(row0 + ld_r + i * 64) * 1024 + kk + ld_c);
            CP_ASYNC16(d + TILE_B,
                       Bh + (size_t)(col0 + ld_r + i * 64) * 1024 + kk + ld_c);
        }
    };

    const int lrow = ((lane >> 3) & 1) * 8 + (lane & 7);
    const int lcol = (lane >> 4) * 8;
    uint32_t a_base[4], b_base[2];
    #pragma unroll
    for (int i = 0; i < 4; i++)
        a_base[i] = (uint32_t)(((wm * 64 + i * 16 + lrow) * APITCH + lcol) * 2);
    #pragma unroll
    for (int j2 = 0; j2 < 2; j2++)
        b_base[j2] = (uint32_t)(TILE_B +
                     ((wn * 32 + j2 * 16 + lrow) * APITCH + lcol) * 2);

    float c[4][4][4];
    #pragma unroll
    for (int i = 0; i < 4; i++)
        #pragma unroll
        for (int j = 0; j < 4; j++)
            #pragma unroll
            for (int r = 0; r < 4; r++) c[i][j][r] = 0.f;

    issue(0); CP_COMMIT();
    issue(1); CP_COMMIT();
    issue(2); CP_COMMIT();

    for (int ch = 0; ch < NCH; ch++) {
        CP_WAIT2();
        __syncthreads();
        const uint32_t st = sb + (ch & (NST - 1)) * STG;
        #pragma unroll
        for (int ks = 0; ks < 2; ks++) {
            const uint32_t ko = (uint32_t)(ks * 16 * 2);
            uint32_t b[2][4];
            #pragma unroll
            for (int j2 = 0; j2 < 2; j2++)
                LDMATRIX_X4(b[j2][0], b[j2][1], b[j2][2], b[j2][3],
                            st + b_base[j2] + ko);
            uint32_t a[4][4];
            #pragma unroll
            for (int i = 0; i < 4; i++)
                LDMATRIX_X4(a[i][0], a[i][1], a[i][2], a[i][3],
                            st + a_base[i] + ko);
            #pragma unroll
            for (int i = 0; i < 4; i++)
                #pragma unroll
                for (int j = 0; j < 4; j++) {
                    const int j2 = j >> 1, hi = j & 1;
                    MMA16816(c[i][j][0], c[i][j][1], c[i][j][2], c[i][j][3],
                             a[i][0], a[i][1], a[i][2], a[i][3],
                             b[j2][hi], b[j2][2 + hi]);
                }
        }
        if (ch + 3 < NCH) issue(ch + 3);
        CP_COMMIT();
    }

    // ---------------- epilogue ----------------
    const int groupID = lane >> 2;
    const int tig = lane & 3;

    #pragma unroll
    for (int j = 0; j < 4; j++) {
        int col = col0 + wn * 32 + j * 8 + tig * 2;
        float bb0 = bias[col], bb1 = bias[col + 1];
        #pragma unroll
        for (int i = 0; i < 4; i++) {
            c[i][j][0] += bb0; c[i][j][1] += bb1;
            c[i][j][2] += bb0; c[i][j][3] += bb1;
        }
    }

    if (z < normFlag) {
        float* ssm = (float*)dsm;   // [4 wn][128 rows]
        float ssq[4][2];
        #pragma unroll
        for (int i = 0; i < 4; i++)
            #pragma unroll
            for (int hf = 0; hf < 2; hf++) {
                float ss = 0.f;
                #pragma unroll
                for (int j = 0; j < 4; j++)
                    ss += c[i][j][2*hf] * c[i][j][2*hf]
                        + c[i][j][2*hf+1] * c[i][j][2*hf+1];
                ss += __shfl_xor_sync(0xFFFFFFFFu, ss, 1);
                ss += __shfl_xor_sync(0xFFFFFFFFu, ss, 2);
                ssq[i][hf] = ss;
            }
        __syncthreads();
        if (tig == 0) {
            #pragma unroll
            for (int i = 0; i < 4; i++)
                #pragma unroll
                for (int hf = 0; hf < 2; hf++)
                    ssm[wn * 128 + wm * 64 + i * 16 + groupID + hf * 8] = ssq[i][hf];
        }
        __syncthreads();
        #pragma unroll
        for (int i = 0; i < 4; i++)
            #pragma unroll
            for (int hf = 0; hf < 2; hf++) {
                int row = wm * 64 + i * 16 + groupID + hf * 8;
                float tot = ssq[i][hf] + ssm[(wn ^ 1) * 128 + row];
                float inv = 1.f / fmaxf(sqrtf(tot), 1e-12f);
                #pragma unroll
                for (int j = 0; j < 4; j++) {
                    c[i][j][2*hf]   *= inv;
                    c[i][j][2*hf+1] *= inv;
                }
            }
    }

    if (fp16out) {
        __half* H = (z == 0) ? H0 : (z == 1) ? H1 : H2;
        #pragma unroll
        for (int i = 0; i < 4; i++) {
            int row = row0 + wm * 64 + i * 16 + groupID;
            #pragma unroll
            for (int j = 0; j < 4; j++) {
                int col = col0 + wn * 32 + j * 8 + tig * 2;
                *(__half2*)(H + (size_t)row * 1024 + col) =
                    __halves2half2(__float2half_rn(c[i][j][0]),
                                   __float2half_rn(c[i][j][1]));
                *(__half2*)(H + (size_t)(row + 8) * 1024 + col) =
                    __halves2half2(__float2half_rn(c[i][j][2]),
                                   __float2half_rn(c[i][j][3]));
            }
        }
    } else {
        #pragma unroll
        for (int i = 0; i < 4; i++) {
            int row = row0 + wm * 64 + i * 16 + groupID;
            #pragma unroll
            for (int j = 0; j < 4; j++) {
                int col = col0 + wn * 32 + j * 8 + tig * 2;
                *(float2*)(C0 + (size_t)row * 1024 + col) =
                    make_float2(c[i][j][0], c[i][j][1]);
                *(float2*)(C0 + (size_t)(row + 8) * 1024 + col) =
                    make_float2(c[i][j][2], c[i][j][3]);
            }
        }
    }
}

// ==================== K^T V via mma, cp.async pipelined ====================
// Per block: (b,h,chunk of 128 tokens) = 2 sub-chunks of 64 tokens,
// 2-stage cp.async (36.9 KB smem -> 4 CTAs/SM, reg-limited).
#define KTV_PITCH 72
#define KTV_MAT_BYTES (64 * KTV_PITCH * 2)       // 9216 per matrix per stage
#define KTV_STG_BYTES (2 * KTV_MAT_BYTES)        // 18432 (K + V)
#define KTV_SMEM (2 * KTV_STG_BYTES)             // 36864

__global__ __launch_bounds__(256) void ktv_mma_kernel(
    const __half* __restrict__ kh, const __half* __restrict__ vh,
    float* __restrict__ Sp)
{
    extern __shared__ __align__(128) char dsm[];
    const uint32_t sbase = (uint32_t)__cvta_generic_to_shared(dsm);

    int blk = blockIdx.x;            // 0..1023 = bh*16 + chunk
    int bh = blk >> 4, chunk = blk & 15;
    int b = bh >> 4, h = bh & 15;
    const __half* kb = kh + ((size_t)b * NTOK + chunk * 128) * FEATS + h * HDIM;
    const __half* vb = vh + ((size_t)b * NTOK + chunk * 128) * FEATS + h * HDIM;

    int tid = threadIdx.x;
    int lane = tid & 31, wid = tid >> 5;
    int ms = wid & 3, tokhalf = wid >> 2;

    // cp.async load of one 64-token sub-chunk (K and V)
    const int ld_r = tid >> 2;            // 0..63 row
    const int ld_c8 = (tid & 3) * 16;     // 2 groups of 8 halfs per thread
    auto issue = [&](int s) {
        uint32_t st = sbase + s * KTV_STG_BYTES;
        const __half* ks = kb + (size_t)(s * 64 + ld_r) * FEATS + ld_c8;
        const __half* vs = vb + (size_t)(s * 64 + ld_r) * FEATS + ld_c8;
        uint32_t d = st + (uint32_t)((ld_r * KTV_PITCH + ld_c8) * 2);
        CP_ASYNC16(d, ks);
        CP_ASYNC16(d + 16, ks + 8);
        CP_ASYNC16(d + KTV_MAT_BYTES, vs);
        CP_ASYNC16(d + KTV_MAT_BYTES + 16, vs + 8);
    };

    // trans-ldmatrix lane addressing (relative to stage K / V bases)
    int g = lane >> 3, l = lane & 7;
    int a_row = ((g >> 1) & 1) * 8 + l;
    int a_col = ms * 16 + (g & 1) * 8;
    int b_row = (g & 1) * 8 + l;
    int b_col = (g >> 1) * 8;
    uint32_t a_rel = (uint32_t)((a_row * KTV_PITCH + a_col) * 2);
    uint32_t b_rel = (uint32_t)(KTV_MAT_BYTES + (b_row * KTV_PITCH + b_col) * 2);

    float c[8][4];
    #pragma unroll
    for (int j = 0; j < 8; j++)
        #pragma unroll
        for (int r = 0; r < 4; r++) c[j][r] = 0.f;

    issue(0); CP_COMMIT();
    issue(1); CP_COMMIT();

    #pragma unroll
    for (int s = 0; s < 2; s++) {
        if (s == 0) { CP_WAIT1(); } else { CP_WAIT0(); }   // last stage provably complete
        __syncthreads();
        uint32_t st = sbase + s * KTV_STG_BYTES;
        #pragma unroll
        for (int step = 0; step < 2; step++) {
            int T0 = tokhalf * 32 + step * 16;
            uint32_t toff = (uint32_t)(T0 * KTV_PITCH * 2);
            uint32_t a0, a1, a2, a3;
            LDMATRIX_X4_T(a0, a1, a2, a3, st + a_rel + toff);
            #pragma unroll
            for (int nt = 0; nt < 4; nt++) {
                uint32_t r0, r1, r2, r3;
                LDMATRIX_X4_T(r0, r1, r2, r3,
                              st + b_rel + toff + (uint32_t)(nt * 16 * 2));
                MMA16816(c[nt*2][0], c[nt*2][1], c[nt*2][2], c[nt*2][3],
                         a0, a1, a2, a3, r0, r1);
                MMA16816(c[nt*2+1][0], c[nt*2+1][1], c[nt*2+1][2], c[nt*2+1][3],
                         a0, a1, a2, a3, r2, r3);
            }
        }
    }

    // in-block reduction of the two token halves
    int groupID = lane >> 2, tig = lane & 3;
    __syncthreads();
    float* red = (float*)dsm;       // 16 KB, reuses stage memory (all MMA done)
    if (tokhalf == 1) {
        #pragma unroll
        for (int j = 0; j < 8; j++) {
            int cc = j * 8 + tig * 2;
            red[ms * 1024 + groupID * 64 + cc]       = c[j][0];
            red[ms * 1024 + groupID * 64 + cc + 1]   = c[j][1];
            red[ms * 1024 + (groupID + 8) * 64 + cc]     = c[j][2];
            red[ms * 1024 + (groupID + 8) * 64 + cc + 1] = c[j][3];
        }
    }
    __syncthreads();
    if (tokhalf == 0) {
        float* Sb = Sp + (size_t)blk * (HDIM * HDIM);
        #pragma unroll
        for (int j = 0; j < 8; j++) {
            int cc = j * 8 + tig * 2;
            int r1 = ms * 16 + groupID, r2 = r1 + 8;
            Sb[r1 * 64 + cc]     = c[j][0] + red[ms * 1024 + groupID * 64 + cc];
            Sb[r1 * 64 + cc + 1] = c[j][1] + red[ms * 1024 + groupID * 64 + cc + 1];
            Sb[r2 * 64 + cc]     = c[j][2] + red[ms * 1024 + (groupID + 8) * 64 + cc];
            Sb[r2 * 64 + cc + 1] = c[j][3] + red[ms * 1024 + (groupID + 8) * 64 + cc + 1];
        }
    }
}

__global__ __launch_bounds__(256) void ktv_reduce_kernel(
    const float* __restrict__ Sp, const float* __restrict__ m,
    float* __restrict__ S)
{
    int bh = blockIdx.x;
    int h = bh & 15;
    float sig = 1.f / (1.f + expf(-m[h]));
    float inv = 1.f / powf((float)NTOK, sig);
    const float* base = Sp + (size_t)bh * 16 * HDIM * HDIM;
    float* out = S + (size_t)bh * HDIM * HDIM;
    for (int e = threadIdx.x; e < HDIM * HDIM; e += 256) {
        float s = 0.f;
        #pragma unroll
        for (int c = 0; c < 16; c++) s += base[c * HDIM * HDIM + e];
        out[e] = s * inv;
    }
}

// ==================== attn = Q @ S ; fp16 in/out (4x4 tile) ====================
__global__ __launch_bounds__(256) void qs_kernel(
    const __half* __restrict__ qh, const float* __restrict__ S,
    __half* __restrict__ ah)
{
    int bh = blockIdx.y;
    int b = bh >> 4, h = bh & 15;
    int row0 = blockIdx.x * 64;

    __shared__ float qT[HDIM][68];   // qT[d][token]
    __shared__ float Ss[HDIM][68];   // Ss[d][col]

    const __half* qb = qh + (size_t)b * NTOK * FEATS + h * HDIM;
    const float* Sb = S + (size_t)bh * HDIM * HDIM;

    int tid = threadIdx.x;
    for (int i = tid; i < HDIM * HDIM; i += 256) {
        int r = i >> 6, cc = i & 63;
        Ss[r][cc] = Sb[i];
    }
    for (int u = tid; u < 512; u += 256) {
        int t = u >> 3, d0 = (u & 7) * 8;
        uint4 raw = *(const uint4*)(qb + (size_t)(row0 + t) * FEATS + d0);
        __half2* hp = (__half2*)&raw;
        #pragma unroll
        for (int p = 0; p < 4; p++) {
            float2 f = __half22float2(hp[p]);
            qT[d0 + p * 2][t]     = f.x;
            qT[d0 + p * 2 + 1][t] = f.y;
        }
    }
    __syncthreads();

    int ty = tid >> 4;
    int tx = tid & 15;

    float acc[4][4];
    #pragma unroll
    for (int a = 0; a < 4; a++)
        #pragma unroll
        for (int bq = 0; bq < 4; bq++) acc[a][bq] = 0.f;

    #pragma unroll 8
    for (int pp = 0; pp < HDIM; pp++) {
        float4 qv = *(float4*)&qT[pp][ty * 4];
        float4 sv = *(float4*)&Ss[pp][tx * 4];
        float qr[4] = {qv.x, qv.y, qv.z, qv.w};
        float sr[4] = {sv.x, sv.y, sv.z, sv.w};
        #pragma unroll
        for (int a = 0; a < 4; a++)
            #pragma unroll
            for (int bq = 0; bq < 4; bq++)
                acc[a][bq] = fmaf(qr[a], sr[bq], acc[a][bq]);
    }

    #pragma unroll
    for (int a = 0; a < 4; a++) {
        size_t off = (size_t)(b * NTOK + row0 + ty * 4 + a) * FEATS + h * HDIM + tx * 4;
        *(__half2*)(ah + off) =
            __halves2half2(__float2half_rn(acc[a][0]), __float2half_rn(acc[a][1]));
        *(__half2*)(ah + off + 2) =
            __halves2half2(__float2half_rn(acc[a][2]), __float2half_rn(acc[a][3]));
    }
}

// ==================== launch ====================
extern "C" void kernel_launch(void* const* d_in, const int* in_sizes, int n_in,
                              void* d_out, int out_size)
{
    const float* x  = (const float*)d_in[0];
    const float* Wq = (const float*)d_in[1];
    const float* bq = (const float*)d_in[2];
    const float* Wk = (const float*)d_in[3];
    const float* bk = (const float*)d_in[4];
    const float* Wv = (const float*)d_in[5];
    const float* bv = (const float*)d_in[6];
    const float* Wo = (const float*)d_in[7];
    const float* bo = (const float*)d_in[8];
    const float* m  = (const float*)d_in[9];
    float* out = (float*)d_out;

    float *S, *Sp;
    __half *xh, *qh, *kh, *vh, *ah, *wth;
    cudaGetSymbolAddress((void**)&S, g_S);
    cudaGetSymbolAddress((void**)&Sp, g_Sp);
    cudaGetSymbolAddress((void**)&xh, g_xh);
    cudaGetSymbolAddress((void**)&qh, g_qh);
    cudaGetSymbolAddress((void**)&kh, g_kh);
    cudaGetSymbolAddress((void**)&vh, g_vh);
    cudaGetSymbolAddress((void**)&ah, g_ah);
    cudaGetSymbolAddress((void**)&wth, g_wth);

    cudaFuncSetAttribute(gemm1_kernel,
                         cudaFuncAttributeMaxDynamicSharedMemorySize, GSMEM);
    cudaFuncSetAttribute(ktv_mma_kernel,
                         cudaFuncAttributeMaxDynamicSharedMemorySize, KTV_SMEM);

    // merged converts: x->fp16 + 4x W transpose->fp16
    prep_kernel<<<12288, 256>>>(x, Wq, Wk, Wv, Wo, xh, wth);

    // fused QKV projections + bias + Q/K L2 norm; fp16 outputs
    gemm1_kernel<<<dim3(1024 / TBN, MROWS / TBM, 3), 256, GSMEM>>>(
        xh, wth, bq, bk, bv, nullptr, qh, kh, vh, 2, 1);

    // S = K^T V (tensor cores, pipelined, 1024 chunks), then scale-reduce
    ktv_mma_kernel<<<1024, 256, KTV_SMEM>>>(kh, vh, Sp);
    ktv_reduce_kernel<<<64, 256>>>(Sp, m, S);

    // attn = Q @ S (fp16 out)
    qs_kernel<<<dim3(NTOK / 64, 64), 256>>>(qh, S, ah);

    // out = attn @ Wo + bo  (single shared Wo -> full L2 reuse)
    gemm1_kernel<<<dim3(1024 / TBN, MROWS / TBM, 1), 256, GSMEM>>>(
        ah, wth + 3 * (size_t)WSZ, bo, bo, bo,
        out, nullptr, nullptr, nullptr, 0, 0);
}

// round 15
// speedup vs baseline: 1.0138x; 1.0138x over previous
#include <cuda_runtime.h>
#include <cuda_fp16.h>
#include <math.h>
#include <stdint.h>

// Problem constants
#define BATCH 4
#define NTOK  2048
#define FEATS 1024
#define NHEAD 16
#define HDIM  64
#define MROWS (BATCH * NTOK)   // 8192
#define WSZ   (1024 * 1024)

// ---------------- scratch (device globals) ----------------
__device__ float  g_S[64 * HDIM * HDIM];
__device__ float  g_Sp[1024 * HDIM * HDIM];   // 16 MB: 16 partials per (b,h)
__device__ __half g_xh[MROWS * FEATS];
__device__ __half g_qh[MROWS * FEATS];
__device__ __half g_kh[MROWS * FEATS];
__device__ __half g_vh[MROWS * FEATS];
__device__ __half g_ah[MROWS * FEATS];
__device__ __half g_wth[4 * WSZ];   // Wq/Wk/Wv/Wo transposed [N,K] fp16

// ==================== PTX helpers ====================
#define CP_ASYNC16(dst, src) \
    asm volatile("cp.async.cg.shared.global [%0], [%1], 16;\n" :: "r"(dst), "l"(src))
#define CP_COMMIT() asm volatile("cp.async.commit_group;\n")
#define CP_WAIT2()  asm volatile("cp.async.wait_group 2;\n" ::: "memory")
#define CP_WAIT1()  asm volatile("cp.async.wait_group 1;\n" ::: "memory")
#define CP_WAIT0()  asm volatile("cp.async.wait_group 0;\n" ::: "memory")

#define LDMATRIX_X4(r0,r1,r2,r3,addr) \
    asm volatile("ldmatrix.sync.aligned.m8n8.x4.shared.b16 {%0,%1,%2,%3}, [%4];" \
        : "=r"(r0),"=r"(r1),"=r"(r2),"=r"(r3) : "r"(addr))
#define LDMATRIX_X4_T(r0,r1,r2,r3,addr) \
    asm volatile("ldmatrix.sync.aligned.m8n8.x4.trans.shared.b16 {%0,%1,%2,%3}, [%4];" \
        : "=r"(r0),"=r"(r1),"=r"(r2),"=r"(r3) : "r"(addr))
#define MMA16816(c0,c1,c2,c3,a0,a1,a2,a3,b0,b1) \
    asm volatile("mma.sync.aligned.m16n8k16.row.col.f32.f16.f16.f32 " \
        "{%0,%1,%2,%3},{%4,%5,%6,%7},{%8,%9},{%0,%1,%2,%3};" \
        : "+f"(c0),"+f"(c1),"+f"(c2),"+f"(c3) \
        : "r"(a0),"r"(a1),"r"(a2),"r"(a3),"r"(b0),"r"(b1))

// ==================== merged prep: x->fp16 + W transpose->fp16 ====================
__global__ __launch_bounds__(256) void prep_kernel(
    const float* __restrict__ x,
    const float* __restrict__ W0, const float* __restrict__ W1,
    const float* __restrict__ W2, const float* __restrict__ W3,
    __half* __restrict__ xh, __half* __restrict__ wth)
{
    __shared__ float t[32][33];
    int bx = blockIdx.x;
    int tid = threadIdx.x;
    if (bx < 8192) {
        int i = bx * 256 + tid;     // exactly MROWS*FEATS/4 elements
        float4 v = ((const float4*)x)[i];
        __half2* hp = (__half2*)xh;
        hp[i*2]   = __half2(__float2half_rn(v.x), __float2half_rn(v.y));
        hp[i*2+1] = __half2(__float2half_rn(v.z), __float2half_rn(v.w));
    } else {
        int wb = bx - 8192;
        int z = wb >> 10;
        int rest = wb & 1023;
        int n0 = (rest & 31) * 32;
        int k0 = (rest >> 5) * 32;
        const float* W = (z == 0) ? W0 : (z == 1) ? W1 : (z == 2) ? W2 : W3;
        __half* ho = wth + (size_t)z * WSZ;
        int tx = tid & 31, ty = tid >> 5;  // 32 x 8
        #pragma unroll
        for (int i = 0; i < 32; i += 8)
            t[ty + i][tx] = W[(size_t)(k0 + ty + i) * 1024 + n0 + tx];
        __syncthreads();
        #pragma unroll
        for (int i = 0; i < 32; i += 8)
            ho[(size_t)(n0 + ty + i) * 1024 + k0 + tx] = __float2half_rn(t[tx][ty + i]);
    }
}

// ==================== mma.sync fp16 GEMM ====================
// C = A @ B^T + bias  (B stored [N,K] fp16)
// Tile 128x128, 8 warps (2M x 4N), warp tile 64x32, chunk K=32, 4-stage.
#define TBM 128
#define TBN 128
#define TKC 32
#define NCH 32
#define APITCH 40
#define TILE_B (128 * APITCH * 2)   // 10240 bytes per tile
#define STG (2 * TILE_B)            // 20480 (A, B)
#define NST 4
#define GSMEM (NST * STG)           // 81920

__global__ __launch_bounds__(256, 2) void gemm1_kernel(
    const __half* __restrict__ Ah, const __half* __restrict__ Wth,
    const float* __restrict__ b0, const float* __restrict__ b1,
    const float* __restrict__ b2,
    float* __restrict__ C0,
    __half* __restrict__ H0, __half* __restrict__ H1, __half* __restrict__ H2,
    int normFlag, int fp16out)
{
    extern __shared__ __align__(128) char dsm[];
    const uint32_t sb = (uint32_t)__cvta_generic_to_shared(dsm);

    const int tid = threadIdx.x;
    const int lane = tid & 31;
    const int wid = tid >> 5;
    const int wm = wid & 1;        // 0..1 -> 64-row half
    const int wn = wid >> 1;       // 0..3 -> 32-col quarter
    const int z = blockIdx.z;
    const int row0 = blockIdx.y * TBM;
    const int col0 = blockIdx.x * TBN;

    const __half* Bh = Wth + (size_t)z * WSZ;
    const float* bias = (z == 0) ? b0 : (z == 1) ? b1 : b2;

    // cp.async addressing
    const int ld_r  = tid >> 2;
    const int ld_c  = (tid & 3) * 8;
    const uint32_t ld_dst = (uint32_t)((ld_r * APITCH + ld_c) * 2);

    auto issue = [&](int c) {
        const int kk = c * TKC;
        const uint32_t st = sb + (c & (NST - 1)) * STG;
        #pragma unroll
        for (int i = 0; i < 2; i++) {
            uint32_t d = st + ld_dst + i * 64 * APITCH * 2;
            CP_ASYNC16(d, Ah + (size_t)(row0 + ld_r + i * 64) * 1024 + kk + ld_c);
            CP_ASYNC16(d + TILE_B,
                       Bh + (size_t)(col0 + ld_r + i * 64) * 1024 + kk + ld_c);
        }
    };

    const int lrow = ((lane >> 3) & 1) * 8 + (lane & 7);
    const int lcol = (lane >> 4) * 8;
    uint32_t a_base[4], b_base[2];
    #pragma unroll
    for (int i = 0; i < 4; i++)
        a_base[i] = (uint32_t)(((wm * 64 + i * 16 + lrow) * APITCH + lcol) * 2);
    #pragma unroll
    for (int j2 = 0; j2 < 2; j2++)
        b_base[j2] = (uint32_t)(TILE_B +
                     ((wn * 32 + j2 * 16 + lrow) * APITCH + lcol) * 2);

    float c[4][4][4];
    #pragma unroll
    for (int i = 0; i < 4; i++)
        #pragma unroll
        for (int j = 0; j < 4; j++)
            #pragma unroll
            for (int r = 0; r < 4; r++) c[i][j][r] = 0.f;

    issue(0); CP_COMMIT();
    issue(1); CP_COMMIT();
    issue(2); CP_COMMIT();

    for (int ch = 0; ch < NCH; ch++) {
        CP_WAIT2();
        __syncthreads();
        const uint32_t st = sb + (ch & (NST - 1)) * STG;
        #pragma unroll
        for (int ks = 0; ks < 2; ks++) {
            const uint32_t ko = (uint32_t)(ks * 16 * 2);
            uint32_t b[2][4];
            #pragma unroll
            for (int j2 = 0; j2 < 2; j2++)
                LDMATRIX_X4(b[j2][0], b[j2][1], b[j2][2], b[j2][3],
                            st + b_base[j2] + ko);
            uint32_t a[4][4];
            #pragma unroll
            for (int i = 0; i < 4; i++)
                LDMATRIX_X4(a[i][0], a[i][1], a[i][2], a[i][3],
                            st + a_base[i] + ko);
            #pragma unroll
            for (int i = 0; i < 4; i++)
                #pragma unroll
                for (int j = 0; j < 4; j++) {
                    const int j2 = j >> 1, hi = j & 1;
                    MMA16816(c[i][j][0], c[i][j][1], c[i][j][2], c[i][j][3],
                             a[i][0], a[i][1], a[i][2], a[i][3],
                             b[j2][hi], b[j2][2 + hi]);
                }
        }
        if (ch + 3 < NCH) issue(ch + 3);
        CP_COMMIT();
    }

    // ---------------- epilogue ----------------
    const int groupID = lane >> 2;
    const int tig = lane & 3;

    #pragma unroll
    for (int j = 0; j < 4; j++) {
        int col = col0 + wn * 32 + j * 8 + tig * 2;
        float bb0 = bias[col], bb1 = bias[col + 1];
        #pragma unroll
        for (int i = 0; i < 4; i++) {
            c[i][j][0] += bb0; c[i][j][1] += bb1;
            c[i][j][2] += bb0; c[i][j][3] += bb1;
        }
    }

    if (z < normFlag) {
        float* ssm = (float*)dsm;   // [4 wn][128 rows]
        float ssq[4][2];
        #pragma unroll
        for (int i = 0; i < 4; i++)
            #pragma unroll
            for (int hf = 0; hf < 2; hf++) {
                float ss = 0.f;
                #pragma unroll
                for (int j = 0; j < 4; j++)
                    ss += c[i][j][2*hf] * c[i][j][2*hf]
                        + c[i][j][2*hf+1] * c[i][j][2*hf+1];
                ss += __shfl_xor_sync(0xFFFFFFFFu, ss, 1);
                ss += __shfl_xor_sync(0xFFFFFFFFu, ss, 2);
                ssq[i][hf] = ss;
            }
        __syncthreads();
        if (tig == 0) {
            #pragma unroll
            for (int i = 0; i < 4; i++)
                #pragma unroll
                for (int hf = 0; hf < 2; hf++)
                    ssm[wn * 128 + wm * 64 + i * 16 + groupID + hf * 8] = ssq[i][hf];
        }
        __syncthreads();
        #pragma unroll
        for (int i = 0; i < 4; i++)
            #pragma unroll
            for (int hf = 0; hf < 2; hf++) {
                int row = wm * 64 + i * 16 + groupID + hf * 8;
                float tot = ssq[i][hf] + ssm[(wn ^ 1) * 128 + row];
                float inv = 1.f / fmaxf(sqrtf(tot), 1e-12f);
                #pragma unroll
                for (int j = 0; j < 4; j++) {
                    c[i][j][2*hf]   *= inv;
                    c[i][j][2*hf+1] *= inv;
                }
            }
    }

    if (fp16out) {
        __half* H = (z == 0) ? H0 : (z == 1) ? H1 : H2;
        #pragma unroll
        for (int i = 0; i < 4; i++) {
            int row = row0 + wm * 64 + i * 16 + groupID;
            #pragma unroll
            for (int j = 0; j < 4; j++) {
                int col = col0 + wn * 32 + j * 8 + tig * 2;
                *(__half2*)(H + (size_t)row * 1024 + col) =
                    __halves2half2(__float2half_rn(c[i][j][0]),
                                   __float2half_rn(c[i][j][1]));
                *(__half2*)(H + (size_t)(row + 8) * 1024 + col) =
                    __halves2half2(__float2half_rn(c[i][j][2]),
                                   __float2half_rn(c[i][j][3]));
            }
        }
    } else {
        #pragma unroll
        for (int i = 0; i < 4; i++) {
            int row = row0 + wm * 64 + i * 16 + groupID;
            #pragma unroll
            for (int j = 0; j < 4; j++) {
                int col = col0 + wn * 32 + j * 8 + tig * 2;
                *(float2*)(C0 + (size_t)row * 1024 + col) =
                    make_float2(c[i][j][0], c[i][j][1]);
                *(float2*)(C0 + (size_t)(row + 8) * 1024 + col) =
                    make_float2(c[i][j][2], c[i][j][3]);
            }
        }
    }
}

// ==================== K^T V via mma, cp.async pipelined ====================
// Per block: (b,h,chunk of 128 tokens) = 2 sub-chunks of 64 tokens, 2-stage.
#define KTV_PITCH 72
#define KTV_MAT_BYTES (64 * KTV_PITCH * 2)       // 9216 per matrix per stage
#define KTV_STG_BYTES (2 * KTV_MAT_BYTES)        // 18432 (K + V)
#define KTV_SMEM (2 * KTV_STG_BYTES)             // 36864

__global__ __launch_bounds__(256) void ktv_mma_kernel(
    const __half* __restrict__ kh, const __half* __restrict__ vh,
    float* __restrict__ Sp)
{
    extern __shared__ __align__(128) char dsm[];
    const uint32_t sbase = (uint32_t)__cvta_generic_to_shared(dsm);

    int blk = blockIdx.x;            // 0..1023 = bh*16 + chunk
    int bh = blk >> 4, chunk = blk & 15;
    int b = bh >> 4, h = bh & 15;
    const __half* kb = kh + ((size_t)b * NTOK + chunk * 128) * FEATS + h * HDIM;
    const __half* vb = vh + ((size_t)b * NTOK + chunk * 128) * FEATS + h * HDIM;

    int tid = threadIdx.x;
    int lane = tid & 31, wid = tid >> 5;
    int ms = wid & 3, tokhalf = wid >> 2;

    const int ld_r = tid >> 2;            // 0..63 row
    const int ld_c8 = (tid & 3) * 16;     // 2 groups of 8 halfs per thread
    auto issue = [&](int s) {
        uint32_t st = sbase + s * KTV_STG_BYTES;
        const __half* ks = kb + (size_t)(s * 64 + ld_r) * FEATS + ld_c8;
        const __half* vs = vb + (size_t)(s * 64 + ld_r) * FEATS + ld_c8;
        uint32_t d = st + (uint32_t)((ld_r * KTV_PITCH + ld_c8) * 2);
        CP_ASYNC16(d, ks);
        CP_ASYNC16(d + 16, ks + 8);
        CP_ASYNC16(d + KTV_MAT_BYTES, vs);
        CP_ASYNC16(d + KTV_MAT_BYTES + 16, vs + 8);
    };

    int g = lane >> 3, l = lane & 7;
    int a_row = ((g >> 1) & 1) * 8 + l;
    int a_col = ms * 16 + (g & 1) * 8;
    int b_row = (g & 1) * 8 + l;
    int b_col = (g >> 1) * 8;
    uint32_t a_rel = (uint32_t)((a_row * KTV_PITCH + a_col) * 2);
    uint32_t b_rel = (uint32_t)(KTV_MAT_BYTES + (b_row * KTV_PITCH + b_col) * 2);

    float c[8][4];
    #pragma unroll
    for (int j = 0; j < 8; j++)
        #pragma unroll
        for (int r = 0; r < 4; r++) c[j][r] = 0.f;

    issue(0); CP_COMMIT();
    issue(1); CP_COMMIT();

    #pragma unroll
    for (int s = 0; s < 2; s++) {
        if (s == 0) { CP_WAIT1(); } else { CP_WAIT0(); }
        __syncthreads();
        uint32_t st = sbase + s * KTV_STG_BYTES;
        #pragma unroll
        for (int step = 0; step < 2; step++) {
            int T0 = tokhalf * 32 + step * 16;
            uint32_t toff = (uint32_t)(T0 * KTV_PITCH * 2);
            uint32_t a0, a1, a2, a3;
            LDMATRIX_X4_T(a0, a1, a2, a3, st + a_rel + toff);
            #pragma unroll
            for (int nt = 0; nt < 4; nt++) {
                uint32_t r0, r1, r2, r3;
                LDMATRIX_X4_T(r0, r1, r2, r3,
                              st + b_rel + toff + (uint32_t)(nt * 16 * 2));
                MMA16816(c[nt*2][0], c[nt*2][1], c[nt*2][2], c[nt*2][3],
                         a0, a1, a2, a3, r0, r1);
                MMA16816(c[nt*2+1][0], c[nt*2+1][1], c[nt*2+1][2], c[nt*2+1][3],
                         a0, a1, a2, a3, r2, r3);
            }
        }
    }

    // in-block reduction of the two token halves
    int groupID = lane >> 2, tig = lane & 3;
    __syncthreads();
    float* red = (float*)dsm;
    if (tokhalf == 1) {
        #pragma unroll
        for (int j = 0; j < 8; j++) {
            int cc = j * 8 + tig * 2;
            red[ms * 1024 + groupID * 64 + cc]       = c[j][0];
            red[ms * 1024 + groupID * 64 + cc + 1]   = c[j][1];
            red[ms * 1024 + (groupID + 8) * 64 + cc]     = c[j][2];
            red[ms * 1024 + (groupID + 8) * 64 + cc + 1] = c[j][3];
        }
    }
    __syncthreads();
    if (tokhalf == 0) {
        float* Sb = Sp + (size_t)blk * (HDIM * HDIM);
        #pragma unroll
        for (int j = 0; j < 8; j++) {
            int cc = j * 8 + tig * 2;
            int r1 = ms * 16 + groupID, r2 = r1 + 8;
            Sb[r1 * 64 + cc]     = c[j][0] + red[ms * 1024 + groupID * 64 + cc];
            Sb[r1 * 64 + cc + 1] = c[j][1] + red[ms * 1024 + groupID * 64 + cc + 1];
            Sb[r2 * 64 + cc]     = c[j][2] + red[ms * 1024 + (groupID + 8) * 64 + cc];
            Sb[r2 * 64 + cc + 1] = c[j][3] + red[ms * 1024 + (groupID + 8) * 64 + cc + 1];
        }
    }
}

// ==================== reduce: 512 CTAs, float4, slice per block ====================
// grid (8, 64): block (e0, bh) sums 16 partials over elements [e0*512, e0*512+512)
__global__ __launch_bounds__(256) void ktv_reduce_kernel(
    const float* __restrict__ Sp, const float* __restrict__ m,
    float* __restrict__ S)
{
    int bh = blockIdx.y;
    int e0 = blockIdx.x * 512;
    int h = bh & 15;
    float sig = 1.f / (1.f + expf(-m[h]));
    float inv = 1.f / powf((float)NTOK, sig);
    const float* base = Sp + (size_t)bh * 16 * HDIM * HDIM + e0;
    float* out = S + (size_t)bh * HDIM * HDIM + e0;

    int e4 = threadIdx.x * 4;    // 512 floats / 4 = 128 float4 slots; threads 0..127 active
    if (e4 >= 512) return;
    float4 s = make_float4(0.f, 0.f, 0.f, 0.f);
    #pragma unroll
    for (int c = 0; c < 16; c++) {
        float4 v = *(const float4*)(base + (size_t)c * HDIM * HDIM + e4);
        s.x += v.x; s.y += v.y; s.z += v.z; s.w += v.w;
    }
    *(float4*)(out + e4) = make_float4(s.x * inv, s.y * inv, s.z * inv, s.w * inv);
}

// ==================== attn = Q @ S ; fp16 in/out (4x4 tile) ====================
__global__ __launch_bounds__(256) void qs_kernel(
    const __half* __restrict__ qh, const float* __restrict__ S,
    __half* __restrict__ ah)
{
    int bh = blockIdx.y;
    int b = bh >> 4, h = bh & 15;
    int row0 = blockIdx.x * 64;

    __shared__ float qT[HDIM][68];   // qT[d][token]
    __shared__ float Ss[HDIM][68];   // Ss[d][col]

    const __half* qb = qh + (size_t)b * NTOK * FEATS + h * HDIM;
    const float* Sb = S + (size_t)bh * HDIM * HDIM;

    int tid = threadIdx.x;
    for (int i = tid; i < HDIM * HDIM; i += 256) {
        int r = i >> 6, cc = i & 63;
        Ss[r][cc] = Sb[i];
    }
    for (int u = tid; u < 512; u += 256) {
        int t = u >> 3, d0 = (u & 7) * 8;
        uint4 raw = *(const uint4*)(qb + (size_t)(row0 + t) * FEATS + d0);
        __half2* hp = (__half2*)&raw;
        #pragma unroll
        for (int p = 0; p < 4; p++) {
            float2 f = __half22float2(hp[p]);
            qT[d0 + p * 2][t]     = f.x;
            qT[d0 + p * 2 + 1][t] = f.y;
        }
    }
    __syncthreads();

    int ty = tid >> 4;
    int tx = tid & 15;

    float acc[4][4];
    #pragma unroll
    for (int a = 0; a < 4; a++)
        #pragma unroll
        for (int bq = 0; bq < 4; bq++) acc[a][bq] = 0.f;

    #pragma unroll 8
    for (int pp = 0; pp < HDIM; pp++) {
        float4 qv = *(float4*)&qT[pp][ty * 4];
        float4 sv = *(float4*)&Ss[pp][tx * 4];
        float qr[4] = {qv.x, qv.y, qv.z, qv.w};
        float sr[4] = {sv.x, sv.y, sv.z, sv.w};
        #pragma unroll
        for (int a = 0; a < 4; a++)
            #pragma unroll
            for (int bq = 0; bq < 4; bq++)
                acc[a][bq] = fmaf(qr[a], sr[bq], acc[a][bq]);
    }

    #pragma unroll
    for (int a = 0; a < 4; a++) {
        size_t off = (size_t)(b * NTOK + row0 + ty * 4 + a) * FEATS + h * HDIM + tx * 4;
        *(__half2*)(ah + off) =
            __halves2half2(__float2half_rn(acc[a][0]), __float2half_rn(acc[a][1]));
        *(__half2*)(ah + off + 2) =
            __halves2half2(__float2half_rn(acc[a][2]), __float2half_rn(acc[a][3]));
    }
}

// ==================== launch ====================
extern "C" void kernel_launch(void* const* d_in, const int* in_sizes, int n_in,
                              void* d_out, int out_size)
{
    const float* x  = (const float*)d_in[0];
    const float* Wq = (const float*)d_in[1];
    const float* bq = (const float*)d_in[2];
    const float* Wk = (const float*)d_in[3];
    const float* bk = (const float*)d_in[4];
    const float* Wv = (const float*)d_in[5];
    const float* bv = (const float*)d_in[6];
    const float* Wo = (const float*)d_in[7];
    const float* bo = (const float*)d_in[8];
    const float* m  = (const float*)d_in[9];
    float* out = (float*)d_out;

    float *S, *Sp;
    __half *xh, *qh, *kh, *vh, *ah, *wth;
    cudaGetSymbolAddress((void**)&S, g_S);
    cudaGetSymbolAddress((void**)&Sp, g_Sp);
    cudaGetSymbolAddress((void**)&xh, g_xh);
    cudaGetSymbolAddress((void**)&qh, g_qh);
    cudaGetSymbolAddress((void**)&kh, g_kh);
    cudaGetSymbolAddress((void**)&vh, g_vh);
    cudaGetSymbolAddress((void**)&ah, g_ah);
    cudaGetSymbolAddress((void**)&wth, g_wth);

    cudaFuncSetAttribute(gemm1_kernel,
                         cudaFuncAttributeMaxDynamicSharedMemorySize, GSMEM);
    cudaFuncSetAttribute(ktv_mma_kernel,
                         cudaFuncAttributeMaxDynamicSharedMemorySize, KTV_SMEM);

    // merged converts: x->fp16 + 4x W transpose->fp16
    prep_kernel<<<12288, 256>>>(x, Wq, Wk, Wv, Wo, xh, wth);

    // fused QKV projections + bias + Q/K L2 norm; fp16 outputs
    gemm1_kernel<<<dim3(1024 / TBN, MROWS / TBM, 3), 256, GSMEM>>>(
        xh, wth, bq, bk, bv, nullptr, qh, kh, vh, 2, 1);

    // S = K^T V (tensor cores, pipelined, 1024 chunks), then scale-reduce
    ktv_mma_kernel<<<1024, 256, KTV_SMEM>>>(kh, vh, Sp);
    ktv_reduce_kernel<<<dim3(8, 64), 256>>>(Sp, m, S);

    // attn = Q @ S (fp16 out)
    qs_kernel<<<dim3(NTOK / 64, 64), 256>>>(qh, S, ah);

    // out = attn @ Wo + bo  (single shared Wo -> full L2 reuse)
    gemm1_kernel<<<dim3(1024 / TBN, MROWS / TBM, 1), 256, GSMEM>>>(
        ah, wth + 3 * (size_t)WSZ, bo, bo, bo,
        out, nullptr, nullptr, nullptr, 0, 0);
}